// round 7
// baseline (speedup 1.0000x reference)
#include <cuda_runtime.h>
#include <cstdint>
#include <cstddef>

// Problem constants
#define BB 4
#define SS 4096
#define HH 16
#define DD 64
#define GM 16384   // B*S
#define GN 1024    // H*D == OUT
#define GK 1024    // IN == H*D

// Intermediate buffers (allocation-free rule: device globals)
__device__ float g_xp[(size_t)GM * GN];  // input projection  [B,S,H*D]
__device__ float g_y [(size_t)GM * GN];  // scan outputs      [B,S,H*D]

// ---------------------------------------------------------------------------
// tf32 helpers
// ---------------------------------------------------------------------------
__device__ __forceinline__ uint32_t f2tf32(float f) {
    uint32_t u;
    asm("cvt.rna.tf32.f32 %0, %1;" : "=r"(u) : "f"(f));
    return u;
}

__device__ __forceinline__ void mma_tf32(float c[4], const uint32_t a[4], const uint32_t b[2]) {
    asm volatile(
        "mma.sync.aligned.m16n8k8.row.col.f32.tf32.tf32.f32 "
        "{%0,%1,%2,%3}, {%4,%5,%6,%7}, {%8,%9}, {%0,%1,%2,%3};"
        : "+f"(c[0]), "+f"(c[1]), "+f"(c[2]), "+f"(c[3])
        : "r"(a[0]), "r"(a[1]), "r"(a[2]), "r"(a[3]), "r"(b[0]), "r"(b[1]));
}

// ---------------------------------------------------------------------------
// GEMM: C[M,N] = A[M,K] * B[N,K]^T   (A row-major, B row-major over K)
// Block tile 128x128, K-tile 32, 256 threads, 8 warps in 4(M) x 2(N),
// warp tile 32(M) x 64(N).  tf32 tensor cores, fp32 accumulate.
// smem layout: rows of 32 floats (8 x float4), float4-slot XOR-swizzled by
// (row & 7)  -> conflict-free for both the staging stores and fragment loads.
// ---------------------------------------------------------------------------
__global__ __launch_bounds__(256) void gemm_tf32(
    const float* __restrict__ A, const float* __restrict__ B, float* __restrict__ C)
{
    __shared__ uint4 As4[128 * 8];
    __shared__ uint4 Bs4[128 * 8];

    const int tid  = threadIdx.x;
    const int warp = tid >> 5;
    const int lane = tid & 31;
    const int wm   = warp >> 1;      // 0..3
    const int wn   = warp & 1;       // 0..1
    const int g    = lane >> 2;      // group 0..7
    const int t4   = lane & 3;       // thread-in-group
    const int lr   = tid >> 3;       // staging row 0..31
    const int lc4  = tid & 7;        // staging float4 col 0..7
    const int bm   = blockIdx.y * 128;
    const int bn   = blockIdx.x * 128;

    const float4* Ag = reinterpret_cast<const float4*>(A) + (size_t)(bm + lr) * (GK / 4) + lc4;
    const float4* Bg = reinterpret_cast<const float4*>(B) + (size_t)(bn + lr) * (GK / 4) + lc4;
    const int sw = lc4 ^ (lr & 7);

    float acc[2][8][4];
#pragma unroll
    for (int mi = 0; mi < 2; ++mi)
#pragma unroll
        for (int ni = 0; ni < 8; ++ni)
#pragma unroll
            for (int r = 0; r < 4; ++r) acc[mi][ni][r] = 0.f;

    // prologue: stage K-tile 0
    float4 pa[4], pb[4];
#pragma unroll
    for (int i = 0; i < 4; ++i) {
        pa[i] = Ag[(size_t)i * 32 * (GK / 4)];
        pb[i] = Bg[(size_t)i * 32 * (GK / 4)];
    }

    const uint32_t* As = reinterpret_cast<const uint32_t*>(As4);
    const uint32_t* Bs = reinterpret_cast<const uint32_t*>(Bs4);
    const uint32_t* Abase = As + (wm * 32 + g) * 32 + t4;
    const uint32_t* Bbase = Bs + (wn * 64 + g) * 32 + t4;

    for (int kt = 0; kt < GK / 32; ++kt) {
        __syncthreads();   // previous compute finished reading smem
#pragma unroll
        for (int i = 0; i < 4; ++i) {
            As4[(lr + 32 * i) * 8 + sw] =
                make_uint4(f2tf32(pa[i].x), f2tf32(pa[i].y), f2tf32(pa[i].z), f2tf32(pa[i].w));
            Bs4[(lr + 32 * i) * 8 + sw] =
                make_uint4(f2tf32(pb[i].x), f2tf32(pb[i].y), f2tf32(pb[i].z), f2tf32(pb[i].w));
        }
        __syncthreads();   // smem tile ready

        if (kt + 1 < GK / 32) {        // prefetch next tile (overlaps compute)
#pragma unroll
            for (int i = 0; i < 4; ++i) {
                pa[i] = Ag[(size_t)(kt + 1) * 8 + (size_t)i * 32 * (GK / 4)];
                pb[i] = Bg[(size_t)(kt + 1) * 8 + (size_t)i * 32 * (GK / 4)];
            }
        }

#pragma unroll
        for (int j = 0; j < 4; ++j) {          // 4 k8-steps per K-tile
            const int x0 = ((2 * j) ^ g) * 4;  // swizzled scalar offset, first half
            uint32_t af[2][4];
#pragma unroll
            for (int mi = 0; mi < 2; ++mi) {
                const uint32_t* p = Abase + mi * 16 * 32;
                af[mi][0] = p[x0];
                af[mi][1] = p[8 * 32 + x0];
                af[mi][2] = p[x0 ^ 4];
                af[mi][3] = p[8 * 32 + (x0 ^ 4)];
            }
#pragma unroll
            for (int ni = 0; ni < 8; ++ni) {
                const uint32_t* p = Bbase + ni * 8 * 32;
                uint32_t bf[2] = { p[x0], p[x0 ^ 4] };
                mma_tf32(acc[0][ni], af[0], bf);
                mma_tf32(acc[1][ni], af[1], bf);
            }
        }
    }

    // epilogue: direct float2 stores
#pragma unroll
    for (int mi = 0; mi < 2; ++mi) {
        const int row = bm + wm * 32 + mi * 16 + g;
#pragma unroll
        for (int ni = 0; ni < 8; ++ni) {
            const int col = bn + wn * 64 + ni * 8 + t4 * 2;
            *reinterpret_cast<float2*>(C + (size_t)row * GN + col) =
                make_float2(acc[mi][ni][0], acc[mi][ni][1]);
            *reinterpret_cast<float2*>(C + (size_t)(row + 8) * GN + col) =
                make_float2(acc[mi][ni][2], acc[mi][ni][3]);
        }
    }
}

// ---------------------------------------------------------------------------
// Recurrent scan: one block per (b,h).  128 threads: thread t handles output
// element e = t>>1, k-half = t&1 (32 MACs each).  h state double-buffered in
// smem -> exactly ONE bar.sync per step.  shfl_xor(1) pairs the two halves.
// x prefetched 2 steps ahead in registers.
// ---------------------------------------------------------------------------
__global__ void __launch_bounds__(128) rnn_scan(
    const float* __restrict__ xp, const float* __restrict__ h0,
    const float* __restrict__ Wst, const float* __restrict__ bias,
    float* __restrict__ y)
{
    const int b    = blockIdx.x >> 4;
    const int h    = blockIdx.x & 15;
    const int t    = threadIdx.x;
    const int e    = t >> 1;
    const int half = t & 1;

    __shared__ __align__(16) float hs[2][64];

    // per-thread weight slice: W[h][e][half*32 .. half*32+31]
    float w[32];
    {
        const float4* wr = reinterpret_cast<const float4*>(
            Wst + ((size_t)(h * 64 + e)) * 64 + half * 32);
#pragma unroll
        for (int c = 0; c < 8; ++c) {
            float4 v = wr[c];
            w[4 * c + 0] = v.x; w[4 * c + 1] = v.y;
            w[4 * c + 2] = v.z; w[4 * c + 3] = v.w;
        }
    }
    const float be = bias[h * 64 + e];

    if (t < 64) hs[0][t] = h0[(size_t)(b * HH + h) * 64 + t];

    const float* xb = xp + (size_t)b * SS * 1024 + h * 64 + e;
    float*       yb = y  + (size_t)b * SS * 1024 + h * 64 + e;

    float xc = xb[0];
    float x1 = xb[1024];
    __syncthreads();

    int cur = 0;
    for (int s = 0; s < SS; ++s) {
        const float4* hv = reinterpret_cast<const float4*>(&hs[cur][half * 32]);
        float a0 = 0.f, a1 = 0.f, a2 = 0.f, a3 = 0.f;
#pragma unroll
        for (int c = 0; c < 8; ++c) {
            float4 q = hv[c];
            a0 = fmaf(w[4 * c + 0], q.x, a0);
            a1 = fmaf(w[4 * c + 1], q.y, a1);
            a2 = fmaf(w[4 * c + 2], q.z, a2);
            a3 = fmaf(w[4 * c + 3], q.w, a3);
        }
        float acc = (a0 + a1) + (a2 + a3);
        acc += __shfl_xor_sync(0xffffffffu, acc, 1);   // both halves get full sum

        const float hn = tanhf(acc + be + xc);

        float xn = 0.f;
        if (s + 2 < SS) xn = xb[(size_t)(s + 2) * 1024];   // distance-2 prefetch

        if (half) yb[(size_t)s * 1024] = hn;     // lane 1 streams output
        else      hs[cur ^ 1][e] = hn;           // lane 0 updates state buffer
        __syncthreads();
        cur ^= 1;
        xc = x1; x1 = xn;
    }
}

// ---------------------------------------------------------------------------
// Launch
// ---------------------------------------------------------------------------
extern "C" void kernel_launch(void* const* d_in, const int* in_sizes, int n_in,
                              void* d_out, int out_size)
{
    const float* x     = (const float*)d_in[0];  // [B,S,IN]
    const float* h0    = (const float*)d_in[1];  // [B,H,D]
    const float* w_in  = (const float*)d_in[2];  // [H*D, IN]
    const float* Wst   = (const float*)d_in[3];  // [H,D,D]
    const float* bias  = (const float*)d_in[4];  // [H,D]
    const float* w_out = (const float*)d_in[5];  // [OUT, H*D]
    float* out = (float*)d_out;                  // [B,S,OUT]

    float *xp = nullptr, *yy = nullptr;
    cudaGetSymbolAddress((void**)&xp, g_xp);
    cudaGetSymbolAddress((void**)&yy, g_y);

    dim3 grid(GN / 128, GM / 128);   // (8, 128)
    gemm_tf32<<<grid, 256>>>(x, w_in, xp);          // input projection
    rnn_scan<<<BB * HH, 128>>>(xp, h0, Wst, bias, yy);  // sequential recurrence
    gemm_tf32<<<grid, 256>>>(yy, w_out, out);       // output projection
}